// round 8
// baseline (speedup 1.0000x reference)
#include <cuda_runtime.h>

// Problem constants (fixed by the dataset)
#define NA 200000          // num authors
#define NP 500000          // num papers
#define NE 2000000         // num writes-edges
#define NL 500000          // num label edges
#define HID 128

// ---------------- device scratch (static, no allocation) ----------------
__device__ float g_B[HID * HID];           // W_author @ W_paper^T
__device__ float g_M[HID * HID];           // W_paper @ B  (collapsed operator)
__device__ float g_u1[HID];                // bias vector for count>0 rows
__device__ float g_u0[HID];                // bias vector for count==0 rows
__device__ float g_v[HID];                 // vector for author_c
__device__ float g_c1c0[2];                // scalars for author_c

// edge sort (by author)
__device__ int g_acnt[NA];
__device__ int g_aoff[NA];
__device__ int g_acur[NA];
__device__ int g_sp[NE];                   // paper id per edge, grouped by author

// label-edge sort (by author)
__device__ int g_lcnt[NA];
__device__ int g_loff[NA];
__device__ int g_lcur[NA];
__device__ int2 g_slab[NL];                // (paper id, original index) grouped by author

// scan temporaries (device-side access only!)
__device__ int g_bsA[512];
__device__ int g_bpA[512];
__device__ int g_bsL[512];
__device__ int g_bpL[512];

// ---------------- packed f32x2 helpers ----------------
__device__ __forceinline__ unsigned long long pack2(float lo, float hi) {
    unsigned long long r;
    asm("mov.b64 %0, {%1, %2};" : "=l"(r) : "f"(lo), "f"(hi));
    return r;
}
__device__ __forceinline__ void unpack2(unsigned long long v, float& lo, float& hi) {
    asm("mov.b64 {%0, %1}, %2;" : "=f"(lo), "=f"(hi) : "l"(v));
}
#define FMA_F32X2(d, a, b, c) \
    asm("fma.rn.f32x2 %0, %1, %2, %3;" : "=l"(d) : "l"(a), "l"(b), "l"(c))

// ---------------- zero histograms ----------------
__global__ void k_zero() {
    int i = blockIdx.x * blockDim.x + threadIdx.x;
    int stride = gridDim.x * blockDim.x;
    for (int j = i; j < NA; j += stride) { g_acnt[j] = 0; g_lcnt[j] = 0; }
}

// ---------------- histograms ----------------
__global__ void k_hist(const int* __restrict__ aid, const int* __restrict__ laid) {
    int i = blockIdx.x * blockDim.x + threadIdx.x;
    int stride = gridDim.x * blockDim.x;
    for (int e = i; e < NE; e += stride)
        atomicAdd(&g_acnt[__ldg(aid + e)], 1);
    for (int e = i; e < NL; e += stride)
        atomicAdd(&g_lcnt[__ldg(laid + e)], 1);
}

// ---------------- two-level exclusive scan (device-side symbol binding ONLY) --------
// __device__ globals must never be passed as kernel args from host code (host
// shadow address != device address; ATS makes the bug silent).
__device__ __forceinline__ void scan1_body(const int* __restrict__ in, int* __restrict__ out,
                                           int* __restrict__ bsum, int n) {
    __shared__ int s[1024];
    int i = blockIdx.x * 1024 + threadIdx.x;
    int v = (i < n) ? in[i] : 0;
    s[threadIdx.x] = v;
    __syncthreads();
    for (int o = 1; o < 1024; o <<= 1) {
        int t = (threadIdx.x >= o) ? s[threadIdx.x - o] : 0;
        __syncthreads();
        s[threadIdx.x] += t;
        __syncthreads();
    }
    if (i < n) out[i] = s[threadIdx.x] - v;  // exclusive
    if (threadIdx.x == 1023) bsum[blockIdx.x] = s[1023];
}

__device__ __forceinline__ void scan2_body(const int* __restrict__ bsum,
                                           int* __restrict__ bpre, int nb) {
    __shared__ int s[512];
    int v = (threadIdx.x < nb) ? bsum[threadIdx.x] : 0;
    s[threadIdx.x] = v;
    __syncthreads();
    for (int o = 1; o < 512; o <<= 1) {
        int t = (threadIdx.x >= o) ? s[threadIdx.x - o] : 0;
        __syncthreads();
        s[threadIdx.x] += t;
        __syncthreads();
    }
    if (threadIdx.x < nb) bpre[threadIdx.x] = s[threadIdx.x] - v;  // exclusive
}

__device__ __forceinline__ void scan3_body(int* __restrict__ off, int* __restrict__ cur,
                                           const int* __restrict__ bpre, int n) {
    int i = blockIdx.x * 1024 + threadIdx.x;
    if (i < n) {
        int o = off[i] + bpre[blockIdx.x];
        off[i] = o;
        cur[i] = o;
    }
}

// merged: grid.y / blockIdx selects which array (both length NA)
__global__ void k_scan1_both() {
    if (blockIdx.y == 0) scan1_body(g_acnt, g_aoff, g_bsA, NA);
    else                 scan1_body(g_lcnt, g_loff, g_bsL, NA);
}
__global__ void k_scan2_both(int nb) {
    if (blockIdx.x == 0) scan2_body(g_bsA, g_bpA, nb);
    else                 scan2_body(g_bsL, g_bpL, nb);
}
__global__ void k_scan3_both() {
    if (blockIdx.y == 0) scan3_body(g_aoff, g_acur, g_bpA, NA);
    else                 scan3_body(g_loff, g_lcur, g_bpL, NA);
}

// ---------------- merged reorder: edges and label edges, both by author ----------------
__global__ void k_reorder(const int* __restrict__ aid, const int* __restrict__ pid,
                          const int* __restrict__ laid, const int* __restrict__ lpid) {
    int i = blockIdx.x * blockDim.x + threadIdx.x;
    int stride = gridDim.x * blockDim.x;
    for (int e = i; e < NE; e += stride) {
        int a = __ldg(aid + e);
        int pos = atomicAdd(&g_acur[a], 1);
        g_sp[pos] = __ldg(pid + e);
    }
    for (int e = i; e < NL; e += stride) {
        int a = __ldg(laid + e);
        int pos = atomicAdd(&g_lcur[a], 1);
        g_slab[pos] = make_int2(__ldg(lpid + e), e);
    }
}

// ---------------- precompute step 1: B = W_author @ W_paper^T ----------------
__global__ void k_prep1(const float* __restrict__ Wp, const float* __restrict__ Wa) {
    __shared__ float wa[HID];
    int m = blockIdx.x;
    int j = threadIdx.x;
    wa[j] = Wa[m * HID + j];
    __syncthreads();
    float s = 0.f;
#pragma unroll 8
    for (int k = 0; k < HID; k++) s += wa[k] * Wp[j * HID + k];
    g_B[m * HID + j] = s;
}

// ---------------- precompute step 2: M = W_paper @ B, plus bias vectors ----------------
__global__ void k_prep2(const float* __restrict__ Wp, const float* __restrict__ bp,
                        const float* __restrict__ Wa, const float* __restrict__ ba) {
    int j = threadIdx.x;
    if (blockIdx.x < HID) {
        __shared__ float wp[HID];
        int i = blockIdx.x;
        wp[j] = Wp[i * HID + j];
        __syncthreads();
        float s = 0.f;
#pragma unroll 8
        for (int m = 0; m < HID; m++) s += wp[m] * g_B[m * HID + j];
        g_M[i * HID + j] = s;
    } else {
        __shared__ float w[HID];
        float s = 0.f;
        for (int k = 0; k < HID; k++) s += Wa[j * HID + k] * bp[k];
        w[j] = s;
        float u0 = 0.f;
        for (int k = 0; k < HID; k++) u0 += ba[k] * Wp[j * HID + k];
        g_u0[j] = u0;
        float u1 = u0;
        for (int m = 0; m < HID; m++) u1 += bp[m] * g_B[m * HID + j];
        g_u1[j] = u1;
        __syncthreads();
        float v = 0.f;
        for (int m = 0; m < HID; m++) v += Wp[j * HID + m] * w[m];
        g_v[j] = v;
        if (j == 0) {
            float c0 = 0.f;
            for (int k = 0; k < HID; k++) c0 += ba[k] * bp[k];
            float c1 = c0;
            for (int m = 0; m < HID; m++) c1 += bp[m] * w[m];
            g_c1c0[0] = c1;
            g_c1c0[1] = c0;
        }
    }
}

// ---------------- FUSED: gather-avg -> transform -> classify ----------------
// 256 threads = 8 warps; 8 authors per group; persistent grid-stride over groups.
// Phase A: warp w gathers author base+w's paper rows, avg in registers,
//          writes s_avg[w], computes ac scalar (avg . v) via warp reduce.
// Phase B: thread (half = tid>>7, col = tid&127) computes g[col] for authors
//          half*4..half*4+3 with the M column register-resident (f32x2 FMA).
// Phase C: warp w streams author base+w's label edges, dotting s_g[w] with
//          gathered paper rows; writes pred at original edge index.
// Only 2 barriers per group (C of group i and A of group i+1 touch disjoint smem).
__global__ void __launch_bounds__(256, 1) k_fused(const float4* __restrict__ x,
                                                  float* __restrict__ out) {
    __shared__ __align__(16) float s_avg[8][HID];
    __shared__ __align__(16) float s_g[8][HID];
    __shared__ float s_ac[8];
    __shared__ int   s_cnt[8];

    const int tid  = threadIdx.x;
    const int wid  = tid >> 5;      // 0..7 = warp / author slot
    const int lane = tid & 31;
    const int half = tid >> 7;      // 0 or 1
    const int col  = tid & 127;

    // --- per-thread constants (loaded once) ---
    unsigned long long Mc[HID / 2];  // (M[2k][col], M[2k+1][col]) packed
#pragma unroll
    for (int kp = 0; kp < HID / 2; kp++)
        Mc[kp] = pack2(g_M[(2 * kp) * HID + col], g_M[(2 * kp + 1) * HID + col]);
    const float u1 = g_u1[col], u0 = g_u0[col];
    const float c1 = g_c1c0[0], c0 = g_c1c0[1];
    const float4 v4 = reinterpret_cast<const float4*>(g_v)[lane];

    float4 (*s_avg4)[32] = reinterpret_cast<float4(*)[32]>(s_avg);
    float4 (*s_g4)[32]   = reinterpret_cast<float4(*)[32]>(s_g);

    for (int base = blockIdx.x * 8; base < NA; base += gridDim.x * 8) {
        int a = base + wid;
        // ---------------- Phase A: gather + average ----------------
        if (a < NA) {
            int s = g_aoff[a];
            int e = (a + 1 < NA) ? g_aoff[a + 1] : NE;
            float4 a0 = make_float4(0.f, 0.f, 0.f, 0.f);
            float4 a1 = make_float4(0.f, 0.f, 0.f, 0.f);
            int i = s;
            for (; i + 4 <= e; i += 4) {
                int p0 = __ldg(g_sp + i + 0);
                int p1 = __ldg(g_sp + i + 1);
                int p2 = __ldg(g_sp + i + 2);
                int p3 = __ldg(g_sp + i + 3);
                float4 v0 = __ldg(x + (size_t)p0 * (HID / 4) + lane);
                float4 v1 = __ldg(x + (size_t)p1 * (HID / 4) + lane);
                float4 v2 = __ldg(x + (size_t)p2 * (HID / 4) + lane);
                float4 v3 = __ldg(x + (size_t)p3 * (HID / 4) + lane);
                a0.x += v0.x + v2.x; a0.y += v0.y + v2.y;
                a0.z += v0.z + v2.z; a0.w += v0.w + v2.w;
                a1.x += v1.x + v3.x; a1.y += v1.y + v3.y;
                a1.z += v1.z + v3.z; a1.w += v1.w + v3.w;
            }
            for (; i < e; i++) {
                int p = __ldg(g_sp + i);
                float4 v = __ldg(x + (size_t)p * (HID / 4) + lane);
                a0.x += v.x; a0.y += v.y; a0.z += v.z; a0.w += v.w;
            }
            int cnt = e - s;
            float inv = (cnt > 0) ? (1.0f / (float)cnt) : 0.f;
            float4 av;
            av.x = (a0.x + a1.x) * inv; av.y = (a0.y + a1.y) * inv;
            av.z = (a0.z + a1.z) * inv; av.w = (a0.w + a1.w) * inv;
            s_avg4[wid][lane] = av;
            // ac = avg . v (+ count-dependent constant)
            float pp = av.x * v4.x + av.y * v4.y + av.z * v4.z + av.w * v4.w;
#pragma unroll
            for (int o = 16; o; o >>= 1) pp += __shfl_down_sync(0xffffffffu, pp, o);
            if (lane == 0) {
                s_ac[wid] = pp + ((cnt > 0) ? c1 : c0);
                s_cnt[wid] = cnt;
            }
        }
        __syncthreads();

        // ---------------- Phase B: transform (4 authors per thread) ----------------
        {
            unsigned long long acc[4];
#pragma unroll
            for (int j = 0; j < 4; j++) acc[j] = pack2(0.f, 0.f);
#pragma unroll
            for (int q = 0; q < 32; q++) {  // q indexes a float4 of avg = 2 k-pairs
                unsigned long long m0 = Mc[2 * q], m1 = Mc[2 * q + 1];
#pragma unroll
                for (int j = 0; j < 4; j++) {
                    float4 av = s_avg4[half * 4 + j][q];  // warp-broadcast read
                    FMA_F32X2(acc[j], pack2(av.x, av.y), m0, acc[j]);
                    FMA_F32X2(acc[j], pack2(av.z, av.w), m1, acc[j]);
                }
            }
#pragma unroll
            for (int j = 0; j < 4; j++) {
                float lo, hi;
                unpack2(acc[j], lo, hi);
                bool has = (s_cnt[half * 4 + j] > 0);
                s_g[half * 4 + j][col] = lo + hi + (has ? u1 : u0);
            }
        }
        __syncthreads();

        // ---------------- Phase C: classify label edges of author base+wid --------
        if (a < NA) {
            int s = g_loff[a];
            int e = (a + 1 < NA) ? g_loff[a + 1] : NL;
            if (s < e) {
                float4 gv = s_g4[wid][lane];
                float ac = s_ac[wid];
                int i = s;
                for (; i + 2 <= e; i += 2) {
                    int2 pe0 = __ldg(g_slab + i);
                    int2 pe1 = __ldg(g_slab + i + 1);
                    float4 x0 = __ldg(x + (size_t)pe0.x * (HID / 4) + lane);
                    float4 x1 = __ldg(x + (size_t)pe1.x * (HID / 4) + lane);
                    float d0 = gv.x * x0.x + gv.y * x0.y + gv.z * x0.z + gv.w * x0.w;
                    float d1 = gv.x * x1.x + gv.y * x1.y + gv.z * x1.z + gv.w * x1.w;
#pragma unroll
                    for (int o = 16; o; o >>= 1) {
                        d0 += __shfl_down_sync(0xffffffffu, d0, o);
                        d1 += __shfl_down_sync(0xffffffffu, d1, o);
                    }
                    if (lane == 0) { out[pe0.y] = d0 + ac; out[pe1.y] = d1 + ac; }
                }
                if (i < e) {
                    int2 pe = __ldg(g_slab + i);
                    float4 xv = __ldg(x + (size_t)pe.x * (HID / 4) + lane);
                    float d = gv.x * xv.x + gv.y * xv.y + gv.z * xv.z + gv.w * xv.w;
#pragma unroll
                    for (int o = 16; o; o >>= 1) d += __shfl_down_sync(0xffffffffu, d, o);
                    if (lane == 0) out[pe.y] = d + ac;
                }
            }
        }
        // NOTE: no barrier needed here — next Phase A writes s_avg/s_ac/s_cnt,
        // which Phase B (guarded by the A->B barrier) re-reads only after all
        // warps pass it; Phase C reads only s_g/s_ac... s_ac IS rewritten by A.
        __syncthreads();  // protect s_ac/s_cnt against next group's Phase A
    }
}

// ---------------- launch ----------------
extern "C" void kernel_launch(void* const* d_in, const int* in_sizes, int n_in,
                              void* d_out, int out_size) {
    const float* paper_x = (const float*)d_in[0];
    const int* aid  = (const int*)d_in[1];
    const int* pid  = (const int*)d_in[2];
    const int* laid = (const int*)d_in[3];
    const int* lpid = (const int*)d_in[4];
    const float* Wp = (const float*)d_in[5];
    const float* bp = (const float*)d_in[6];
    const float* Wa = (const float*)d_in[7];
    const float* ba = (const float*)d_in[8];
    float* out = (float*)d_out;

    k_zero<<<512, 256>>>();
    k_hist<<<2048, 256>>>(aid, laid);

    {
        int nb = (NA + 1023) / 1024;
        k_scan1_both<<<dim3(nb, 2), 1024>>>();
        k_scan2_both<<<2, 512>>>(nb);
        k_scan3_both<<<dim3(nb, 2), 1024>>>();
    }

    k_reorder<<<2048, 256>>>(aid, pid, laid, lpid);

    k_prep1<<<HID, HID>>>(Wp, Wa);
    k_prep2<<<HID + 1, HID>>>(Wp, bp, Wa, ba);

    k_fused<<<304, 256>>>((const float4*)paper_x, out);
}

// round 9
// speedup vs baseline: 1.9848x; 1.9848x over previous
#include <cuda_runtime.h>

// Problem constants (fixed by the dataset)
#define NA 200000          // num authors
#define NP 500000          // num papers
#define NE 2000000         // num writes-edges
#define NL 500000          // num label edges
#define HID 128

// ---------------- device scratch (static, no allocation) ----------------
__device__ float g_acc[(size_t)NA * HID];  // author avg-x -> reused as author_g
__device__ float g_ac[NA];                 // author_c scalar per author
__device__ float g_B[HID * HID];           // W_author @ W_paper^T
__device__ float g_M[HID * HID];           // W_paper @ B  (collapsed operator)
__device__ float g_u1[HID];                // bias vector for count>0 rows
__device__ float g_u0[HID];                // bias vector for count==0 rows
__device__ float g_v[HID];                 // vector for author_c
__device__ float g_c1c0[2];                // scalars for author_c

// edge sort (by author)
__device__ int g_acnt[NA];
__device__ int g_aoff[NA];
__device__ int g_acur[NA];
__device__ int g_sp[NE];                   // paper id per edge, grouped by author

// label-edge sort (by author)
__device__ int g_lcnt[NA];
__device__ int g_loff[NA];
__device__ int g_lcur[NA];
__device__ int2 g_slab[NL];                // (paper id, original index) grouped by author

// scan temporaries (device-side access only!)
__device__ int g_bsA[512];
__device__ int g_bpA[512];
__device__ int g_bsL[512];
__device__ int g_bpL[512];

// ---------------- packed f32x2 helpers ----------------
__device__ __forceinline__ unsigned long long pack2(float lo, float hi) {
    unsigned long long r;
    asm("mov.b64 %0, {%1, %2};" : "=l"(r) : "f"(lo), "f"(hi));
    return r;
}
__device__ __forceinline__ void unpack2(unsigned long long v, float& lo, float& hi) {
    asm("mov.b64 {%0, %1}, %2;" : "=f"(lo), "=f"(hi) : "l"(v));
}
#define FMA_F32X2(d, a, b, c) \
    asm("fma.rn.f32x2 %0, %1, %2, %3;" : "=l"(d) : "l"(a), "l"(b), "l"(c))

// ---------------- zero histograms ----------------
__global__ void k_zero() {
    int i = blockIdx.x * blockDim.x + threadIdx.x;
    int stride = gridDim.x * blockDim.x;
    for (int j = i; j < NA; j += stride) { g_acnt[j] = 0; g_lcnt[j] = 0; }
}

// ---------------- histograms ----------------
__global__ void k_hist(const int* __restrict__ aid, const int* __restrict__ laid) {
    int i = blockIdx.x * blockDim.x + threadIdx.x;
    int stride = gridDim.x * blockDim.x;
    for (int e = i; e < NE; e += stride)
        atomicAdd(&g_acnt[__ldg(aid + e)], 1);
    for (int e = i; e < NL; e += stride)
        atomicAdd(&g_lcnt[__ldg(laid + e)], 1);
}

// ---------------- two-level exclusive scan (device-side symbol binding ONLY) --------
// __device__ globals must never be passed as kernel args from host code (host
// shadow address != device address; ATS makes the bug silent).
__device__ __forceinline__ void scan1_body(const int* __restrict__ in, int* __restrict__ out,
                                           int* __restrict__ bsum, int n) {
    __shared__ int s[1024];
    int i = blockIdx.x * 1024 + threadIdx.x;
    int v = (i < n) ? in[i] : 0;
    s[threadIdx.x] = v;
    __syncthreads();
    for (int o = 1; o < 1024; o <<= 1) {
        int t = (threadIdx.x >= o) ? s[threadIdx.x - o] : 0;
        __syncthreads();
        s[threadIdx.x] += t;
        __syncthreads();
    }
    if (i < n) out[i] = s[threadIdx.x] - v;  // exclusive
    if (threadIdx.x == 1023) bsum[blockIdx.x] = s[1023];
}

__device__ __forceinline__ void scan2_body(const int* __restrict__ bsum,
                                           int* __restrict__ bpre, int nb) {
    __shared__ int s[512];
    int v = (threadIdx.x < nb) ? bsum[threadIdx.x] : 0;
    s[threadIdx.x] = v;
    __syncthreads();
    for (int o = 1; o < 512; o <<= 1) {
        int t = (threadIdx.x >= o) ? s[threadIdx.x - o] : 0;
        __syncthreads();
        s[threadIdx.x] += t;
        __syncthreads();
    }
    if (threadIdx.x < nb) bpre[threadIdx.x] = s[threadIdx.x] - v;  // exclusive
}

__device__ __forceinline__ void scan3_body(int* __restrict__ off, int* __restrict__ cur,
                                           const int* __restrict__ bpre, int n) {
    int i = blockIdx.x * 1024 + threadIdx.x;
    if (i < n) {
        int o = off[i] + bpre[blockIdx.x];
        off[i] = o;
        cur[i] = o;
    }
}

// merged: grid.y selects which array (both length NA)
__global__ void k_scan1_both() {
    if (blockIdx.y == 0) scan1_body(g_acnt, g_aoff, g_bsA, NA);
    else                 scan1_body(g_lcnt, g_loff, g_bsL, NA);
}
__global__ void k_scan2_both(int nb) {
    if (blockIdx.x == 0) scan2_body(g_bsA, g_bpA, nb);
    else                 scan2_body(g_bsL, g_bpL, nb);
}
__global__ void k_scan3_both() {
    if (blockIdx.y == 0) scan3_body(g_aoff, g_acur, g_bpA, NA);
    else                 scan3_body(g_loff, g_lcur, g_bpL, NA);
}

// ---------------- merged reorder ----------------
__global__ void k_reorder(const int* __restrict__ aid, const int* __restrict__ pid,
                          const int* __restrict__ laid, const int* __restrict__ lpid) {
    int i = blockIdx.x * blockDim.x + threadIdx.x;
    int stride = gridDim.x * blockDim.x;
    for (int e = i; e < NE; e += stride) {
        int a = __ldg(aid + e);
        int pos = atomicAdd(&g_acur[a], 1);
        g_sp[pos] = __ldg(pid + e);
    }
    for (int e = i; e < NL; e += stride) {
        int a = __ldg(laid + e);
        int pos = atomicAdd(&g_lcur[a], 1);
        g_slab[pos] = make_int2(__ldg(lpid + e), e);
    }
}

// ---------------- precompute step 1: B = W_author @ W_paper^T ----------------
__global__ void k_prep1(const float* __restrict__ Wp, const float* __restrict__ Wa) {
    __shared__ float wa[HID];
    int m = blockIdx.x;
    int j = threadIdx.x;
    wa[j] = Wa[m * HID + j];
    __syncthreads();
    float s = 0.f;
#pragma unroll 8
    for (int k = 0; k < HID; k++) s += wa[k] * Wp[j * HID + k];
    g_B[m * HID + j] = s;
}

// ---------------- precompute step 2: M = W_paper @ B, plus bias vectors ----------------
__global__ void k_prep2(const float* __restrict__ Wp, const float* __restrict__ bp,
                        const float* __restrict__ Wa, const float* __restrict__ ba) {
    int j = threadIdx.x;
    if (blockIdx.x < HID) {
        __shared__ float wp[HID];
        int i = blockIdx.x;
        wp[j] = Wp[i * HID + j];
        __syncthreads();
        float s = 0.f;
#pragma unroll 8
        for (int m = 0; m < HID; m++) s += wp[m] * g_B[m * HID + j];
        g_M[i * HID + j] = s;
    } else {
        __shared__ float w[HID];
        float s = 0.f;
        for (int k = 0; k < HID; k++) s += Wa[j * HID + k] * bp[k];
        w[j] = s;
        float u0 = 0.f;
        for (int k = 0; k < HID; k++) u0 += ba[k] * Wp[j * HID + k];
        g_u0[j] = u0;
        float u1 = u0;
        for (int m = 0; m < HID; m++) u1 += bp[m] * g_B[m * HID + j];
        g_u1[j] = u1;
        __syncthreads();
        float v = 0.f;
        for (int m = 0; m < HID; m++) v += Wp[j * HID + m] * w[m];
        g_v[j] = v;
        if (j == 0) {
            float c0 = 0.f;
            for (int k = 0; k < HID; k++) c0 += ba[k] * bp[k];
            float c1 = c0;
            for (int m = 0; m < HID; m++) c1 += bp[m] * w[m];
            g_c1c0[0] = c1;
            g_c1c0[1] = c0;
        }
    }
}

// ---------------- gather-average: warp per author, 8-deep load pipeline ----------------
__global__ void k_gather_avg(const float4* __restrict__ x) {
    int w = (int)(((size_t)blockIdx.x * blockDim.x + threadIdx.x) >> 5);
    int lane = threadIdx.x & 31;
    if (w >= NA) return;
    int s = g_aoff[w];
    int e = (w + 1 < NA) ? g_aoff[w + 1] : NE;

    float4 a0 = make_float4(0.f, 0.f, 0.f, 0.f);
    float4 a1 = make_float4(0.f, 0.f, 0.f, 0.f);
    int i = s;
    for (; i + 8 <= e; i += 8) {
        float4 v0 = __ldg(x + (size_t)__ldg(g_sp + i + 0) * (HID / 4) + lane);
        float4 v1 = __ldg(x + (size_t)__ldg(g_sp + i + 1) * (HID / 4) + lane);
        float4 v2 = __ldg(x + (size_t)__ldg(g_sp + i + 2) * (HID / 4) + lane);
        float4 v3 = __ldg(x + (size_t)__ldg(g_sp + i + 3) * (HID / 4) + lane);
        float4 v4 = __ldg(x + (size_t)__ldg(g_sp + i + 4) * (HID / 4) + lane);
        float4 v5 = __ldg(x + (size_t)__ldg(g_sp + i + 5) * (HID / 4) + lane);
        float4 v6 = __ldg(x + (size_t)__ldg(g_sp + i + 6) * (HID / 4) + lane);
        float4 v7 = __ldg(x + (size_t)__ldg(g_sp + i + 7) * (HID / 4) + lane);
        a0.x += (v0.x + v2.x) + (v4.x + v6.x);
        a0.y += (v0.y + v2.y) + (v4.y + v6.y);
        a0.z += (v0.z + v2.z) + (v4.z + v6.z);
        a0.w += (v0.w + v2.w) + (v4.w + v6.w);
        a1.x += (v1.x + v3.x) + (v5.x + v7.x);
        a1.y += (v1.y + v3.y) + (v5.y + v7.y);
        a1.z += (v1.z + v3.z) + (v5.z + v7.z);
        a1.w += (v1.w + v3.w) + (v5.w + v7.w);
    }
    for (; i + 2 <= e; i += 2) {
        float4 v0 = __ldg(x + (size_t)__ldg(g_sp + i + 0) * (HID / 4) + lane);
        float4 v1 = __ldg(x + (size_t)__ldg(g_sp + i + 1) * (HID / 4) + lane);
        a0.x += v0.x; a0.y += v0.y; a0.z += v0.z; a0.w += v0.w;
        a1.x += v1.x; a1.y += v1.y; a1.z += v1.z; a1.w += v1.w;
    }
    if (i < e) {
        float4 v = __ldg(x + (size_t)__ldg(g_sp + i) * (HID / 4) + lane);
        a0.x += v.x; a0.y += v.y; a0.z += v.z; a0.w += v.w;
    }
    float inv = (e > s) ? (1.0f / (float)(e - s)) : 0.f;
    float4 acc;
    acc.x = (a0.x + a1.x) * inv;
    acc.y = (a0.y + a1.y) * inv;
    acc.z = (a0.z + a1.z) * inv;
    acc.w = (a0.w + a1.w) * inv;
    reinterpret_cast<float4*>(g_acc)[(size_t)w * (HID / 4) + lane] = acc;
}

// ---------------- per-author transform: 4 rows per barrier pair, f32x2 FMA ----------
// NA % 4 == 0. Thread tid owns output column tid; M column register-resident.
__global__ void __launch_bounds__(128, 3) k_transform() {
    __shared__ __align__(16) float s_avg[4][HID];
    __shared__ float s_red[4][4];   // [row][warp]
    __shared__ int   s_cnt[4];
    const int tid = threadIdx.x;
    const int wrp = tid >> 5;
    const int lane = tid & 31;

    unsigned long long Mc[HID / 2];  // (M[2k][tid], M[2k+1][tid])
#pragma unroll
    for (int kp = 0; kp < HID / 2; kp++)
        Mc[kp] = pack2(g_M[(2 * kp) * HID + tid], g_M[(2 * kp + 1) * HID + tid]);
    const float u1 = g_u1[tid], u0 = g_u0[tid], vv = g_v[tid];
    const float c1 = g_c1c0[0], c0 = g_c1c0[1];

    const float4 (*s_avg4)[32] = reinterpret_cast<const float4(*)[32]>(s_avg);
    const int ngrp = NA / 4;

    for (int grp = blockIdx.x; grp < ngrp; grp += gridDim.x) {
        int row0 = grp * 4;
        float aval[4];
        float pp[4];
#pragma unroll
        for (int j = 0; j < 4; j++) {
            aval[j] = g_acc[(size_t)(row0 + j) * HID + tid];
            s_avg[j][tid] = aval[j];
            pp[j] = aval[j] * vv;
        }
        if (tid < 4) {
            int r = row0 + tid;
            int rs = g_aoff[r];
            int re = (r + 1 < NA) ? g_aoff[r + 1] : NE;
            s_cnt[tid] = re - rs;
        }
        // 4 interleaved warp reductions
#pragma unroll
        for (int o = 16; o; o >>= 1) {
            pp[0] += __shfl_down_sync(0xffffffffu, pp[0], o);
            pp[1] += __shfl_down_sync(0xffffffffu, pp[1], o);
            pp[2] += __shfl_down_sync(0xffffffffu, pp[2], o);
            pp[3] += __shfl_down_sync(0xffffffffu, pp[3], o);
        }
        if (lane == 0) {
#pragma unroll
            for (int j = 0; j < 4; j++) s_red[j][wrp] = pp[j];
        }
        __syncthreads();

        unsigned long long acc[4];
#pragma unroll
        for (int j = 0; j < 4; j++) acc[j] = pack2(0.f, 0.f);
#pragma unroll
        for (int q = 0; q < 32; q++) {
            unsigned long long m0 = Mc[2 * q], m1 = Mc[2 * q + 1];
#pragma unroll
            for (int j = 0; j < 4; j++) {
                float4 av = s_avg4[j][q];  // smem broadcast
                FMA_F32X2(acc[j], pack2(av.x, av.y), m0, acc[j]);
                FMA_F32X2(acc[j], pack2(av.z, av.w), m1, acc[j]);
            }
        }
#pragma unroll
        for (int j = 0; j < 4; j++) {
            float lo, hi;
            unpack2(acc[j], lo, hi);
            bool has = (s_cnt[j] > 0);
            g_acc[(size_t)(row0 + j) * HID + tid] = lo + hi + (has ? u1 : u0);
        }
        if (tid < 4) {
            bool has = (s_cnt[tid] > 0);
            g_ac[row0 + tid] = s_red[tid][0] + s_red[tid][1] + s_red[tid][2] + s_red[tid][3]
                               + (has ? c1 : c0);
        }
        __syncthreads();  // protect s_avg/s_red/s_cnt before next group
    }
}

// ---------------- classifier: warp per author, 4-wide unroll ----------------
__global__ void k_classify(const float4* __restrict__ x, float* __restrict__ out) {
    int w = (int)(((size_t)blockIdx.x * blockDim.x + threadIdx.x) >> 5);
    int lane = threadIdx.x & 31;
    if (w >= NA) return;
    int s = g_loff[w];
    int e = (w + 1 < NA) ? g_loff[w + 1] : NL;
    if (s == e) return;
    float4 gv = reinterpret_cast<const float4*>(g_acc)[(size_t)w * (HID / 4) + lane];
    float ac = g_ac[w];
    int i = s;
    for (; i + 4 <= e; i += 4) {
        int2 pe0 = __ldg(g_slab + i + 0);
        int2 pe1 = __ldg(g_slab + i + 1);
        int2 pe2 = __ldg(g_slab + i + 2);
        int2 pe3 = __ldg(g_slab + i + 3);
        float4 x0 = __ldg(x + (size_t)pe0.x * (HID / 4) + lane);
        float4 x1 = __ldg(x + (size_t)pe1.x * (HID / 4) + lane);
        float4 x2 = __ldg(x + (size_t)pe2.x * (HID / 4) + lane);
        float4 x3 = __ldg(x + (size_t)pe3.x * (HID / 4) + lane);
        float d0 = gv.x * x0.x + gv.y * x0.y + gv.z * x0.z + gv.w * x0.w;
        float d1 = gv.x * x1.x + gv.y * x1.y + gv.z * x1.z + gv.w * x1.w;
        float d2 = gv.x * x2.x + gv.y * x2.y + gv.z * x2.z + gv.w * x2.w;
        float d3 = gv.x * x3.x + gv.y * x3.y + gv.z * x3.z + gv.w * x3.w;
#pragma unroll
        for (int o = 16; o; o >>= 1) {
            d0 += __shfl_down_sync(0xffffffffu, d0, o);
            d1 += __shfl_down_sync(0xffffffffu, d1, o);
            d2 += __shfl_down_sync(0xffffffffu, d2, o);
            d3 += __shfl_down_sync(0xffffffffu, d3, o);
        }
        if (lane == 0) {
            out[pe0.y] = d0 + ac; out[pe1.y] = d1 + ac;
            out[pe2.y] = d2 + ac; out[pe3.y] = d3 + ac;
        }
    }
    for (; i < e; i++) {
        int2 pe = __ldg(g_slab + i);
        float4 xv = __ldg(x + (size_t)pe.x * (HID / 4) + lane);
        float d = gv.x * xv.x + gv.y * xv.y + gv.z * xv.z + gv.w * xv.w;
#pragma unroll
        for (int o = 16; o; o >>= 1) d += __shfl_down_sync(0xffffffffu, d, o);
        if (lane == 0) out[pe.y] = d + ac;
    }
}

// ---------------- launch ----------------
extern "C" void kernel_launch(void* const* d_in, const int* in_sizes, int n_in,
                              void* d_out, int out_size) {
    const float* paper_x = (const float*)d_in[0];
    const int* aid  = (const int*)d_in[1];
    const int* pid  = (const int*)d_in[2];
    const int* laid = (const int*)d_in[3];
    const int* lpid = (const int*)d_in[4];
    const float* Wp = (const float*)d_in[5];
    const float* bp = (const float*)d_in[6];
    const float* Wa = (const float*)d_in[7];
    const float* ba = (const float*)d_in[8];
    float* out = (float*)d_out;

    k_zero<<<512, 256>>>();
    k_hist<<<2048, 256>>>(aid, laid);

    {
        int nb = (NA + 1023) / 1024;
        k_scan1_both<<<dim3(nb, 2), 1024>>>();
        k_scan2_both<<<2, 512>>>(nb);
        k_scan3_both<<<dim3(nb, 2), 1024>>>();
    }

    k_reorder<<<2048, 256>>>(aid, pid, laid, lpid);

    k_prep1<<<HID, HID>>>(Wp, Wa);
    k_prep2<<<HID + 1, HID>>>(Wp, bp, Wa, ba);

    k_gather_avg<<<(NA + 7) / 8, 256>>>((const float4*)paper_x);
    k_transform<<<444, 128>>>();
    k_classify<<<(NA + 7) / 8, 256>>>((const float4*)paper_x, out);
}